// round 16
// baseline (speedup 1.0000x reference)
#include <cuda_runtime.h>
#include <math_constants.h>
#include <math.h>

// Scratch (no allocs allowed).
#define MAX_BLOCKS 8192
#define MAX_PIX 262144          // supports S up to 512
#define MAX_S 512
__device__ float g_partial[MAX_BLOCKS];
__device__ float g_invmax;
__device__ float g_W[MAX_PIX];  // per-pixel integer winding count (as float)

__device__ __forceinline__ float hw_tanh(float x) {
    float r;
    asm("tanh.approx.f32 %0, %1;" : "=f"(r) : "f"(x));
    return r;
}

// Rare-path correction: tanh(k*cross)*theta_clamped - sign(cross)*theta_true.
// The identity sign uses a Kahan-compensated cross (sign-exact for nonzero
// true cross), so it always matches the fp64 scanline crossing count.
__device__ __forceinline__ float corr_term(float dx0, float dy0,
                                           float dx1, float dy1, float crossv) {
    const float k = 100000.0f;
    const float ANG_LO = 4.472136e-3f;   // acos(1-1e-5)
    const float ANG_HI = 3.1371205f;     // pi - acos(1-1e-5)
    float dotv = fmaf(dx0, dx1, dy0 * dy1);
    float ay = fabsf(crossv);
    float ax = fabsf(dotv);
    float num = fminf(ax, ay);
    float den = fmaxf(fmaxf(ax, ay), 1e-37f);
    float a = __fdividef(num, den);
    bool big = a > 0.41421356f;
    float ar = __fdividef(a - 1.0f, a + 1.0f);
    float xx = big ? ar : a;
    float z = xx * xx;
    float pl = fmaf(fmaf(fmaf(8.05374449538e-2f, z,
                              -1.38776856032e-1f), z,
                         1.99777106478e-1f), z,
                    -3.33329491539e-1f);
    float r = fmaf(xx * z, pl, xx);
    if (big) r += 0.78539816340f;
    if (ay > ax) r = 1.57079632679f - r;
    if (dotv < 0.0f) r = 3.14159265359f - r;
    float rc = fminf(fmaxf(r, ANG_LO), ANG_HI);
    float sgn = hw_tanh(k * crossv);
    // sign-exact cross via Kahan 2-product
    float pprod = dx0 * dy1;
    float ekah = fmaf(dx0, dy1, -pprod);
    float hkah = fmaf(dy0, dx1, -pprod);
    float acc = hkah - ekah;
    float signed_t = (acc < 0.0f) ? -r : r;
    return fmaf(sgn, rc, -signed_t);
}

// Kernel 0: scanline winding. One block per column (fixed py). For each edge
// straddling y=py, the crossing threshold x_int = num/D (fp64) marks where
// W jumps; accumulate range-updates over rows, prefix, store W[row*Sv+col].
__global__ void scan_kernel(const float2* __restrict__ contour, int N,
                            int Sv, float invS) {
    __shared__ int delta[MAX_S + 1];
    const int col = blockIdx.x;
    const int tid = threadIdx.x;
    const float py = (float)col * invS;      // same expr as main kernel

    for (int i = tid; i <= Sv; i += blockDim.x) delta[i] = 0;
    __syncthreads();

    for (int j = tid; j < N; j += blockDim.x) {
        float2 c0 = contour[j];
        float2 c1 = contour[(j + 1 < N) ? j + 1 : 0];
        double dy0 = (double)c0.y - (double)py;  // sign matches fp32 sub exactly
        double dy1 = (double)c1.y - (double)py;
        bool gt0 = dy0 > 0.0;
        bool gt1 = dy1 > 0.0;
        if (gt0 == gt1) continue;
        int dir = gt0 ? 1 : -1;
        double num = dy0 * (double)c1.x - dy1 * (double)c0.x;
        double D = dy0 - dy1;                    // nonzero (strict straddle)
        double x_int = num / D;
        // estimate last row with px < x_int, then exact-adjust
        double re = fmin(fmax(x_int * (double)Sv, -2.0), (double)Sv + 1.0);
        int r = (int)re;
        if (r < -1) r = -1;
        if (r > Sv - 1) r = Sv - 1;
        // test(r): px_r*D < num (D>0) / > num (D<0), px_r = fl(r*invS)
        #define ROW_TEST(rr) ({                                   \
            double pxd = (double)((float)(rr) * invS);            \
            (D > 0.0) ? (pxd * D < num) : (pxd * D > num); })
        while (r < Sv - 1 && ROW_TEST(r + 1)) r++;
        while (r >= 0 && !ROW_TEST(r)) r--;
        #undef ROW_TEST
        if (r >= 0) {
            atomicAdd(&delta[0], dir);
            atomicAdd(&delta[r + 1], -dir);
        }
    }
    __syncthreads();

    if (tid == 0) {
        int acc = 0;
        for (int r = 0; r < Sv; r++) { acc += delta[r]; delta[r] = acc; }
    }
    __syncthreads();

    for (int r = tid; r < Sv; r += blockDim.x)
        g_W[r * Sv + col] = (float)delta[r];
}

// Kernel 1: TWO threads per pixel, each half of the vertex pairs (R14 shape).
// No straddle/W logic in the loop — W comes from the scanline pre-pass.
__global__ __launch_bounds__(256) void prod_kernel(
    const float2* __restrict__ contour, int N,
    int Sv, float invS, float* __restrict__ out) {
    extern __shared__ char sraw[];
    float2* s_part = (float2*)sraw;                      // 128 combine slots
    float2* sc = (float2*)(sraw + 128 * sizeof(float2)); // N+1 vertices
    __shared__ float warp_red[8];

    const int tid = threadIdx.x;
    for (int i = tid; i <= N; i += blockDim.x)
        sc[i] = contour[i == N ? 0 : i];
    __syncthreads();

    const int warp = tid >> 5;
    const int lane = tid & 31;
    const int half = warp >> 2;                        // 0 or 1
    const int pix_in_blk = ((warp & 3) << 5) + lane;   // 0..127
    const int p = blockIdx.x * 128 + pix_in_blk;
    const int npix = Sv * Sv;
    const bool active = p < npix;
    const int split = N >> 1;
    const int jbeg = half ? split : 0;
    const int jend = half ? N : split;

    float mn2 = CUDART_INF_F, wc = 0.0f;
    float val = -CUDART_INF_F;
    float Wf = 0.0f;
    if (active && half == 0) Wf = g_W[p];   // hoisted: latency hidden by loop

    if (active) {
        const float px = (float)(p / Sv) * invS;
        const float py = (float)(p % Sv) * invS;
        const float K2 = 2.1e-5f;      // covers acos clamp (sin^2 < 2e-5) + 5%
        const float CMIN2 = 1.1e-8f;   // covers unsaturated tanh (|c| < 1e-4)

        float2 c0 = sc[jbeg];
        float dx0 = c0.x - px;
        float dy0 = c0.y - py;
        float d2p = fmaf(dx0, dx0, dy0 * dy0);
        mn2 = d2p;

        #pragma unroll 4
        for (int j = jbeg; j < jend; j++) {
            float2 c = sc[j + 1];
            float dx1 = c.x - px;
            float dy1 = c.y - py;
            float d2 = fmaf(dx1, dx1, dy1 * dy1);
            mn2 = fminf(mn2, d2);
            float crossv = fmaf(dy0, dx1, -dx0 * dy1);
            float cr2 = crossv * crossv;
            float tau2 = fmaf(d2p * d2, K2, CMIN2);
            if (cr2 < tau2)
                wc += corr_term(dx0, dy0, dx1, dy1, crossv);
            dx0 = dx1; dy0 = dy1; d2p = d2;
        }
    }

    // Combine the two halves through smem.
    if (half == 1 && active)
        s_part[pix_in_blk] = make_float2(mn2, wc);
    __syncthreads();
    if (half == 0 && active) {
        float2 o = s_part[pix_in_blk];
        mn2 = fminf(mn2, o.x);
        wc += o.y;
        val = fmaf(6.283185307179586f, Wf, wc)
              * 0.15915494309189535f * sqrtf(mn2);
        out[p] = val;
    }

    // Block max reduction (half-1 threads hold -inf).
    float m = val;
    #pragma unroll
    for (int o = 16; o > 0; o >>= 1)
        m = fmaxf(m, __shfl_xor_sync(0xffffffffu, m, o));
    if (lane == 0) warp_red[warp] = m;
    __syncthreads();
    if (tid == 0) {
        float bm = warp_red[0];
        #pragma unroll
        for (int i = 1; i < 8; i++) bm = fmaxf(bm, warp_red[i]);
        g_partial[blockIdx.x] = bm;
    }
}

// Kernel 2: reduce block partials -> 1/max (single block).
__global__ void max_kernel(int nb) {
    __shared__ float red[32];
    float m = -CUDART_INF_F;
    for (int i = threadIdx.x; i < nb; i += blockDim.x)
        m = fmaxf(m, g_partial[i]);
    #pragma unroll
    for (int o = 16; o > 0; o >>= 1)
        m = fmaxf(m, __shfl_xor_sync(0xffffffffu, m, o));
    if ((threadIdx.x & 31) == 0) red[threadIdx.x >> 5] = m;
    __syncthreads();
    if (threadIdx.x == 0) {
        float bm = red[0];
        int nw = blockDim.x >> 5;
        for (int i = 1; i < nw; i++) bm = fmaxf(bm, red[i]);
        g_invmax = 1.0f / bm;
    }
}

// Kernel 3: normalize (vectorized float4; block 0 covers scalar tail).
__global__ void norm_kernel(float4* __restrict__ out4, float* __restrict__ outf,
                            int nvec, int npix) {
    const float inv = g_invmax;
    int i = blockIdx.x * blockDim.x + threadIdx.x;
    if (i < nvec) {
        float4 v = out4[i];
        v.x *= inv; v.y *= inv; v.z *= inv; v.w *= inv;
        out4[i] = v;
    }
    int tail = npix - nvec * 4;
    if (blockIdx.x == 0 && threadIdx.x < tail)
        outf[nvec * 4 + threadIdx.x] *= inv;
}

extern "C" void kernel_launch(void* const* d_in, const int* in_sizes, int n_in,
                              void* d_out, int out_size) {
    const float2* contour = (const float2*)d_in[0];
    const int N = in_sizes[0] / 2;   // (N, 2) float32
    int Sv = (int)(sqrt((double)out_size) + 0.5);
    float invS = 1.0f / (float)Sv;
    int npix = Sv * Sv;

    float* out = (float*)d_out;
    int blocks = (npix + 127) / 128;               // 1152 for S=384
    size_t smem = 128 * sizeof(float2) + (size_t)(N + 1) * sizeof(float2);

    scan_kernel<<<Sv, 128>>>(contour, N, Sv, invS);
    prod_kernel<<<blocks, 256, smem>>>(contour, N, Sv, invS, out);
    max_kernel<<<1, 1024>>>(blocks);

    int nvec = npix / 4;
    int nthr = 256;
    int vb = (nvec + nthr - 1) / nthr;
    if (vb < 1) vb = 1;
    norm_kernel<<<vb, nthr>>>((float4*)out, out, nvec, npix);
}

// round 17
// speedup vs baseline: 1.1221x; 1.1221x over previous
#include <cuda_runtime.h>
#include <math_constants.h>
#include <math.h>

// Scratch (no allocs allowed): order-preserving-encoded global max.
__device__ unsigned int g_maxu;

__device__ __forceinline__ unsigned fkey(float f) {
    unsigned b = __float_as_uint(f);
    return (b & 0x80000000u) ? ~b : (b | 0x80000000u);
}
__device__ __forceinline__ float funkey(unsigned u) {
    unsigned b = (u & 0x80000000u) ? (u ^ 0x80000000u) : ~u;
    return __uint_as_float(b);
}

__device__ __forceinline__ float hw_tanh(float x) {
    float r;
    asm("tanh.approx.f32 %0, %1;" : "=f"(r) : "f"(x));
    return r;
}

// Rare-path correction: tanh(k*cross)*theta_clamped - sign(cross)*theta_true
__device__ __forceinline__ float corr_term(float dx0, float dy0,
                                           float dx1, float dy1, float crossv) {
    const float k = 100000.0f;
    const float ANG_LO = 4.472136e-3f;   // acos(1-1e-5)
    const float ANG_HI = 3.1371205f;     // pi - acos(1-1e-5)
    float dotv = fmaf(dx0, dx1, dy0 * dy1);
    float ay = fabsf(crossv);
    float ax = fabsf(dotv);
    float num = fminf(ax, ay);
    float den = fmaxf(fmaxf(ax, ay), 1e-37f);
    float a = __fdividef(num, den);
    bool big = a > 0.41421356f;
    float ar = __fdividef(a - 1.0f, a + 1.0f);
    float xx = big ? ar : a;
    float z = xx * xx;
    float pl = fmaf(fmaf(fmaf(8.05374449538e-2f, z,
                              -1.38776856032e-1f), z,
                         1.99777106478e-1f), z,
                    -3.33329491539e-1f);
    float r = fmaf(xx * z, pl, xx);
    if (big) r += 0.78539816340f;
    if (ay > ax) r = 1.57079632679f - r;
    if (dotv < 0.0f) r = 3.14159265359f - r;
    float rc = fminf(fmaxf(r, ANG_LO), ANG_HI);
    float sgn = hw_tanh(k * crossv);
    float signed_t = (crossv < 0.0f) ? -r : r;
    return fmaf(sgn, rc, -signed_t);
}

// Kernel 0: reset global max key.
__global__ void init_kernel() { g_maxu = 0u; }

// Kernel 1 (R14 core, unchanged loop): TWO threads per pixel, each half of
// the vertex pairs. Warp-level half assignment keeps sc[j] loads broadcast.
// Block max folded into a single atomicMax per block (no max kernel).
__global__ __launch_bounds__(256) void prod_kernel(
    const float2* __restrict__ contour, int N,
    int Sv, float invS, float* __restrict__ out) {
    extern __shared__ char sraw[];
    float4* s_part = (float4*)sraw;                    // 128 combine slots
    float2* sc = (float2*)(sraw + 128 * sizeof(float4)); // N+1 vertices
    __shared__ float warp_red[8];

    const int tid = threadIdx.x;
    for (int i = tid; i <= N; i += blockDim.x)
        sc[i] = contour[i == N ? 0 : i];
    __syncthreads();

    const int warp = tid >> 5;
    const int lane = tid & 31;
    const int half = warp >> 2;                 // 0 or 1
    const int pix_in_blk = ((warp & 3) << 5) + lane;
    const int p = blockIdx.x * 128 + pix_in_blk;
    const int npix = Sv * Sv;
    const int split = N >> 1;
    const int jbeg = half ? split : 0;
    const int jend = half ? N : split;
    const bool active = p < npix;

    float mn2 = CUDART_INF_F, wc = 0.0f;
    int W = 0;
    float val = -CUDART_INF_F;

    if (active) {
        const float px = (float)(p / Sv) * invS;
        const float py = (float)(p % Sv) * invS;
        const float HC = 2.30e-3f;
        const float CMIN = 1.0e-4f;

        float2 c0 = sc[jbeg];
        float dx0 = c0.x - px;
        float dy0 = c0.y - py;
        float d2p = fmaf(dx0, dx0, dy0 * dy0);
        mn2 = d2p;
        bool g0 = dy0 > 0.0f;

        #pragma unroll 4
        for (int j = jbeg; j < jend; j++) {
            float2 c = sc[j + 1];
            float dx1 = c.x - px;
            float dy1 = c.y - py;
            float d2 = fmaf(dx1, dx1, dy1 * dy1);
            mn2 = fminf(mn2, d2);
            float crossv = fmaf(dy0, dx1, -dx0 * dy1);

            bool g1 = dy1 > 0.0f;
            if (g0 != g1) {
                if (g0) { if (crossv > 0.0f) W++; }
                else    { if (crossv < 0.0f) W--; }
            }

            // conservative trigger: s*HC + CMIN >= max(CMIN, s*HC);
            // spurious triggers yield exactly-zero corrections.
            float tau = fmaf(d2p + d2, HC, CMIN);
            if (fabsf(crossv) < tau)
                wc += corr_term(dx0, dy0, dx1, dy1, crossv);

            dx0 = dx1; dy0 = dy1; d2p = d2; g0 = g1;
        }
    }

    // Combine the two halves through smem.
    if (half == 1 && active)
        s_part[pix_in_blk] = make_float4(mn2, wc, (float)W, 0.0f);
    __syncthreads();
    if (half == 0 && active) {
        float4 o = s_part[pix_in_blk];
        mn2 = fminf(mn2, o.x);
        wc += o.y;
        W += (int)o.z;
        val = fmaf(6.283185307179586f, (float)W, wc)
              * 0.15915494309189535f * sqrtf(mn2);
        out[p] = val;
    }

    // Block max reduction (half-1 threads hold -inf), then one atomic.
    float m = val;
    #pragma unroll
    for (int o = 16; o > 0; o >>= 1)
        m = fmaxf(m, __shfl_xor_sync(0xffffffffu, m, o));
    if (lane == 0) warp_red[warp] = m;
    __syncthreads();
    if (tid == 0) {
        float bm = warp_red[0];
        #pragma unroll
        for (int i = 1; i < 8; i++) bm = fmaxf(bm, warp_red[i]);
        atomicMax(&g_maxu, fkey(bm));
    }
}

// Kernel 2: normalize. One float per thread (max latency-hiding warps).
__global__ __launch_bounds__(256) void norm_kernel(float* __restrict__ out,
                                                   int npix) {
    const float inv = 1.0f / funkey(g_maxu);
    int i = blockIdx.x * blockDim.x + threadIdx.x;
    if (i < npix) out[i] *= inv;
}

extern "C" void kernel_launch(void* const* d_in, const int* in_sizes, int n_in,
                              void* d_out, int out_size) {
    const float2* contour = (const float2*)d_in[0];
    const int N = in_sizes[0] / 2;   // (N, 2) float32
    int Sv = (int)(sqrt((double)out_size) + 0.5);
    float invS = 1.0f / (float)Sv;
    int npix = Sv * Sv;

    float* out = (float*)d_out;
    int blocks = (npix + 127) / 128;               // 1152 for S=384
    size_t smem = 128 * sizeof(float4) + (size_t)(N + 1) * sizeof(float2);

    init_kernel<<<1, 1>>>();
    prod_kernel<<<blocks, 256, smem>>>(contour, N, Sv, invS, out);
    norm_kernel<<<(npix + 255) / 256, 256>>>(out, npix);
}